// round 8
// baseline (speedup 1.0000x reference)
#include <cuda_runtime.h>
#include <cstdint>

// Problem constants
#define BB 8
#define CC 64
#define NN 100000
#define RR 32
#define VV (RR*RR*RR)                  // 32768 voxels
#define VOX_ELEMS ((size_t)BB*CC*VV)   // 16,777,216 floats

// ---------------- device scratch (no allocations allowed) ----------------
// Channel-contiguous sums: [B][V][C] as float4 groups -> 16B-aligned for red.v4.
// INVARIANT: zero at module load (CUDA zero-init), and k_finalize restores it
// to zero after consuming it, so every kernel_launch (and graph replay) starts
// from a zeroed scratch without a dedicated zero-fill kernel.
__device__ float4   g_scratch[(size_t)BB * VV * (CC/4)];   // 67 MB
__device__ unsigned g_count[BB * VV];                      // 1 MB
__device__ float    g_mean[BB * 3];

// ---------------- K1: per-(batch,axis) mean, fp64, broken dep chain -------
// 24 blocks x 512 threads; 4 independent accumulators per thread so the
// serial DADD chain is ~49 long instead of ~390 (this was the 50us tail).
__global__ void __launch_bounds__(512) k_mean(const float* __restrict__ coords) {
    int row = blockIdx.x;                 // 0..23 = b*3 + axis
    const float* p = coords + (size_t)row * NN;
    int t = threadIdx.x;

    double s0 = 0.0, s1 = 0.0, s2 = 0.0, s3 = 0.0;
    int base = 0;
    for (; base + 2048 <= NN; base += 2048) {
        s0 += (double)__ldcs(p + base + t);
        s1 += (double)__ldcs(p + base + 512 + t);
        s2 += (double)__ldcs(p + base + 1024 + t);
        s3 += (double)__ldcs(p + base + 1536 + t);
    }
    for (int i = base + t; i < NN; i += 512) s0 += (double)__ldcs(p + i);
    double s = (s0 + s1) + (s2 + s3);

    __shared__ double sm[512];
    sm[t] = s;
    __syncthreads();
    for (int off = 256; off > 0; off >>= 1) {
        if (t < off) sm[t] += sm[t + off];
        __syncthreads();
    }
    if (t == 0) g_mean[row] = (float)(sm[0] / (double)NN);
}

// ---------------- K2: norm coords + scatter-add (red.v4) ------------------
__device__ __forceinline__ void red_add_v4(float4* gptr, float a, float b, float c, float d) {
    asm volatile("red.global.add.v4.f32 [%0], {%1,%2,%3,%4};"
                 :: "l"(__cvta_generic_to_global(gptr)),
                    "f"(a), "f"(b), "f"(c), "f"(d)
                 : "memory");
}

__global__ void __launch_bounds__(512) k_scatter(const float* __restrict__ features,
                                                 const float* __restrict__ coords,
                                                 float* __restrict__ norm_out) {
    int gid = blockIdx.x * 512 + threadIdx.x;     // over B*N jointly
    if (gid >= BB * NN) return;
    int b = gid / NN;
    int n = gid - b * NN;

    const float* cb = coords + (size_t)b * 3 * NN;
    // streaming loads: keep these out of L2 so g_scratch stays resident there
    float x = __ldcs(cb + n);
    float y = __ldcs(cb + NN + n);
    float z = __ldcs(cb + 2 * NN + n);

    float mx = g_mean[b*3 + 0];
    float my = g_mean[b*3 + 1];
    float mz = g_mean[b*3 + 2];

    // norm = clip(((c - mean) + 1)/2 * R, 0, R-1)  (scalings are powers of 2 -> exact)
    float sx = fminf(fmaxf((x - mx + 1.0f) * 0.5f * (float)RR, 0.0f), (float)(RR-1));
    float sy = fminf(fmaxf((y - my + 1.0f) * 0.5f * (float)RR, 0.0f), (float)(RR-1));
    float sz = fminf(fmaxf((z - mz + 1.0f) * 0.5f * (float)RR, 0.0f), (float)(RR-1));

    float* nb = norm_out + (size_t)b * 3 * NN;
    __stcs(nb + n,          sx);
    __stcs(nb + NN + n,     sy);
    __stcs(nb + 2 * NN + n, sz);

    // round-half-to-even like jnp.round
    int ix = (int)rintf(sx);
    int iy = (int)rintf(sy);
    int iz = (int)rintf(sz);
    int idx = ix * (RR*RR) + iy * RR + iz;

    atomicAdd(&g_count[b * VV + idx], 1u);

    const float* fb = features + (size_t)b * CC * NN + n;
    float4* dst = &g_scratch[((size_t)b * VV + idx) * (CC/4)];
#pragma unroll
    for (int c4 = 0; c4 < CC/4; c4++) {
        float a0 = __ldcs(fb + (size_t)(c4*4 + 0) * NN);
        float a1 = __ldcs(fb + (size_t)(c4*4 + 1) * NN);
        float a2 = __ldcs(fb + (size_t)(c4*4 + 2) * NN);
        float a3 = __ldcs(fb + (size_t)(c4*4 + 3) * NN);
        red_add_v4(dst + c4, a0, a1, a2, a3);
    }
}

// ---------------- K3: divide + transpose [V][C] -> [C][V], restore zeros --
__global__ void k_finalize(float* __restrict__ vox_out) {
    int b  = blockIdx.y;
    int v0 = blockIdx.x * 64;
    int t  = threadIdx.x;              // 0..255

    __shared__ float tile[64 * 65];
    __shared__ float cnt[64];

    if (t < 64) {
        unsigned c = g_count[b * VV + v0 + t];
        cnt[t] = fmaxf((float)c, 1.0f);
        g_count[b * VV + v0 + t] = 0u;         // restore zero-invariant
    }

    const float* src = (const float*)g_scratch + ((size_t)b * VV + v0) * CC;
#pragma unroll
    for (int r = 0; r < 16; r++) {
        int vv = r * 4 + (t >> 6);
        int c  = t & 63;
        tile[vv * 65 + c] = src[(size_t)vv * CC + c];
    }
    __syncthreads();   // all reads of this block's scratch slice done

    // restore zero-invariant for scratch (vectorized, 1024 float4 per block)
    float4* szero = &g_scratch[((size_t)b * VV + v0) * (CC/4)];
    float4 z4 = make_float4(0.f, 0.f, 0.f, 0.f);
#pragma unroll
    for (int r = 0; r < 4; r++) szero[r * 256 + t] = z4;

    float* ob = vox_out + ((size_t)b * CC) * VV + v0;
#pragma unroll
    for (int r = 0; r < 16; r++) {
        int c  = r * 4 + (t >> 6);
        int vv = t & 63;
        __stcs(ob + (size_t)c * VV + vv, tile[vv * 65 + c] / cnt[vv]);
    }
}

// ---------------- launch ---------------------------------------------------
extern "C" void kernel_launch(void* const* d_in, const int* in_sizes, int n_in,
                              void* d_out, int out_size) {
    const float* features = (const float*)d_in[0];   // [B, C, N]
    const float* coords   = (const float*)d_in[1];   // [B, 3, N]
    float* vox_out  = (float*)d_out;                 // [B, C, 32, 32, 32]
    float* norm_out = (float*)d_out + VOX_ELEMS;     // [B, 3, N]

    k_mean<<<BB * 3, 512>>>(coords);

    int total = BB * NN;
    k_scatter<<<(total + 511) / 512, 512>>>(features, coords, norm_out);

    dim3 fg(VV / 64, BB);
    k_finalize<<<fg, 256>>>(vox_out);
}

// round 12
// speedup vs baseline: 1.3138x; 1.3138x over previous
#include <cuda_runtime.h>
#include <cstdint>

// Problem constants
#define BB 8
#define CC 64
#define NN 100000
#define RR 32
#define VV (RR*RR*RR)                  // 32768 voxels
#define VOX_ELEMS ((size_t)BB*CC*VV)   // 16,777,216 floats

// ---------------- device scratch (no allocations allowed) ----------------
// Channel-contiguous sums: [B][V][C] as float4 groups -> 16B-aligned for red.v4.
// INVARIANT: zero at module load (CUDA zero-init), and k_finalize restores it
// to zero after consuming it, so every kernel_launch (and graph replay) starts
// from a zeroed scratch without a dedicated zero-fill kernel.
__device__ float4   g_scratch[(size_t)BB * VV * (CC/4)];   // 67 MB
__device__ unsigned g_count[BB * VV];                      // 1 MB
__device__ float    g_mean[BB * 3];

// ---------------- K1: per-(batch,axis) mean ------------------------------
// FP64 on sm_103a is throughput-gated (~18.4 cyc/warp-inst/SM) -> the old
// fp64 inner loop cost 63us on 24 SMs regardless of chain splitting.
// New: fp32 accumulation over float4 lanes (4 independent chains), promote
// to double ONLY for the 1024-way block reduction. Deterministic order.
__global__ void __launch_bounds__(1024) k_mean(const float* __restrict__ coords) {
    int row = blockIdx.x;                 // 0..23 = b*3 + axis
    const float4* p = (const float4*)(coords + (size_t)row * NN);  // 25000 float4, 16B-aligned
    int t = threadIdx.x;

    float ax = 0.f, ay = 0.f, az = 0.f, aw = 0.f;
    for (int i = t; i < NN / 4; i += 1024) {
        float4 v = __ldcs(p + i);
        ax += v.x; ay += v.y; az += v.z; aw += v.w;
    }
    double s = ((double)ax + (double)ay) + ((double)az + (double)aw);

    __shared__ double sm[1024];
    sm[t] = s;
    __syncthreads();
    for (int off = 512; off > 0; off >>= 1) {
        if (t < off) sm[t] += sm[t + off];
        __syncthreads();
    }
    if (t == 0) g_mean[row] = (float)(sm[0] / (double)NN);
}

// ---------------- K2: norm coords + scatter-add (red.v4) ------------------
__device__ __forceinline__ void red_add_v4(float4* gptr, float a, float b, float c, float d) {
    asm volatile("red.global.add.v4.f32 [%0], {%1,%2,%3,%4};"
                 :: "l"(__cvta_generic_to_global(gptr)),
                    "f"(a), "f"(b), "f"(c), "f"(d)
                 : "memory");
}

__global__ void __launch_bounds__(512) k_scatter(const float* __restrict__ features,
                                                 const float* __restrict__ coords,
                                                 float* __restrict__ norm_out) {
    int gid = blockIdx.x * 512 + threadIdx.x;     // over B*N jointly
    if (gid >= BB * NN) return;
    int b = gid / NN;
    int n = gid - b * NN;

    const float* cb = coords + (size_t)b * 3 * NN;
    // streaming loads: keep these out of L2 so g_scratch stays resident there
    float x = __ldcs(cb + n);
    float y = __ldcs(cb + NN + n);
    float z = __ldcs(cb + 2 * NN + n);

    float mx = g_mean[b*3 + 0];
    float my = g_mean[b*3 + 1];
    float mz = g_mean[b*3 + 2];

    // norm = clip(((c - mean) + 1)/2 * R, 0, R-1)  (scalings are powers of 2 -> exact)
    float sx = fminf(fmaxf((x - mx + 1.0f) * 0.5f * (float)RR, 0.0f), (float)(RR-1));
    float sy = fminf(fmaxf((y - my + 1.0f) * 0.5f * (float)RR, 0.0f), (float)(RR-1));
    float sz = fminf(fmaxf((z - mz + 1.0f) * 0.5f * (float)RR, 0.0f), (float)(RR-1));

    float* nb = norm_out + (size_t)b * 3 * NN;
    __stcs(nb + n,          sx);
    __stcs(nb + NN + n,     sy);
    __stcs(nb + 2 * NN + n, sz);

    // round-half-to-even like jnp.round
    int ix = (int)rintf(sx);
    int iy = (int)rintf(sy);
    int iz = (int)rintf(sz);
    int idx = ix * (RR*RR) + iy * RR + iz;

    atomicAdd(&g_count[b * VV + idx], 1u);

    const float* fb = features + (size_t)b * CC * NN + n;
    float4* dst = &g_scratch[((size_t)b * VV + idx) * (CC/4)];
#pragma unroll
    for (int c4 = 0; c4 < CC/4; c4++) {
        float a0 = __ldcs(fb + (size_t)(c4*4 + 0) * NN);
        float a1 = __ldcs(fb + (size_t)(c4*4 + 1) * NN);
        float a2 = __ldcs(fb + (size_t)(c4*4 + 2) * NN);
        float a3 = __ldcs(fb + (size_t)(c4*4 + 3) * NN);
        red_add_v4(dst + c4, a0, a1, a2, a3);
    }
}

// ---------------- K3: divide + transpose [V][C] -> [C][V], restore zeros --
__global__ void k_finalize(float* __restrict__ vox_out) {
    int b  = blockIdx.y;
    int v0 = blockIdx.x * 64;
    int t  = threadIdx.x;              // 0..255

    __shared__ float tile[64 * 65];
    __shared__ float cnt[64];

    if (t < 64) {
        unsigned c = g_count[b * VV + v0 + t];
        cnt[t] = fmaxf((float)c, 1.0f);
        g_count[b * VV + v0 + t] = 0u;         // restore zero-invariant
    }

    const float* src = (const float*)g_scratch + ((size_t)b * VV + v0) * CC;
#pragma unroll
    for (int r = 0; r < 16; r++) {
        int vv = r * 4 + (t >> 6);
        int c  = t & 63;
        tile[vv * 65 + c] = src[(size_t)vv * CC + c];
    }
    __syncthreads();   // all reads of this block's scratch slice done

    // restore zero-invariant for scratch (vectorized, 1024 float4 per block)
    float4* szero = &g_scratch[((size_t)b * VV + v0) * (CC/4)];
    float4 z4 = make_float4(0.f, 0.f, 0.f, 0.f);
#pragma unroll
    for (int r = 0; r < 4; r++) szero[r * 256 + t] = z4;

    float* ob = vox_out + ((size_t)b * CC) * VV + v0;
#pragma unroll
    for (int r = 0; r < 16; r++) {
        int c  = r * 4 + (t >> 6);
        int vv = t & 63;
        __stcs(ob + (size_t)c * VV + vv, tile[vv * 65 + c] / cnt[vv]);
    }
}

// ---------------- launch ---------------------------------------------------
extern "C" void kernel_launch(void* const* d_in, const int* in_sizes, int n_in,
                              void* d_out, int out_size) {
    const float* features = (const float*)d_in[0];   // [B, C, N]
    const float* coords   = (const float*)d_in[1];   // [B, 3, N]
    float* vox_out  = (float*)d_out;                 // [B, C, 32, 32, 32]
    float* norm_out = (float*)d_out + VOX_ELEMS;     // [B, 3, N]

    k_mean<<<BB * 3, 1024>>>(coords);

    int total = BB * NN;
    k_scatter<<<(total + 511) / 512, 512>>>(features, coords, norm_out);

    dim3 fg(VV / 64, BB);
    k_finalize<<<fg, 256>>>(vox_out);
}